// round 15
// baseline (speedup 1.0000x reference)
#include <cuda_runtime.h>
#include <cuda_bf16.h>
#include <cstdint>

// R15: AR(24) closed-form GEMM on mma.sync.m16n8k16 (bf16 split, fp32 acc).
// R14 passed (rel_err 4.5e-6) but was overhead-bound: B staging cost ~336
// ops/thread (LDG+STS+LDS) for an operand IDENTICAL across all CTAs.
// R15: prep emits B directly in fragment-ready layout; main kernel loads B
// fragments with 42 LDG.128 from an L1-resident 21.5KB buffer. A staging,
// MMA, and epilogue transpose are byte-identical to the R14-verified code.
//
// Shapes: x [256,336,512] f32, W [24,1] f32, b [1] f32, out [256,168,512] f32

#define ORDER 24
#define KPAD  32
#define T_OUT 168
#define D_DIM 512
#define B_DIM 256
#define S_DIM 336

#define CTA_ROWS 64
#define THREADS  128          // 4 warps; warp w owns rows w*16..w*16+15
#define KP 40                 // padded k-stride (bf16) for As
#define CP 173                // padded t-stride (f32) for Cs (odd -> no conflicts)
#define NT 21                 // n-tiles of 8 along t

#define AS_LO (CTA_ROWS * KP)             // offset of Alo within As (bf16 units)
#define SM_BYTES  44288                   // Cs = 64*173*4; As (10.2KB) overlays

__device__ __nv_bfloat16 d_Bhi[T_OUT * KPAD];
__device__ __nv_bfloat16 d_Blo[T_OUT * KPAD];
__device__ uint4 d_Bfrag[NT * 2 * 32];    // [nt][ks][lane] = {bh0, bh1, bl0, bl1}

static __device__ __forceinline__ unsigned short bf16_bits(__nv_bfloat16 v) {
    unsigned short u; __builtin_memcpy(&u, &v, 2); return u;
}
static __device__ __forceinline__ unsigned pack2(__nv_bfloat16 lo, __nv_bfloat16 hi) {
    return ((unsigned)bf16_bits(hi) << 16) | (unsigned)bf16_bits(lo);
}

// ---- prep (1 warp). Phase 1: coefficient rows via shfl recurrence (R12/R14
// verified). Phase 2: repack into MMA fragment-ready uint4 layout.
__global__ void ar_prep_kernel(const float* __restrict__ W,
                               const float* __restrict__ bias) {
    const int lane = threadIdx.x;
    const float bval = __ldg(bias);
    const float wlane = (lane < ORDER) ? __ldg(&W[lane]) : 0.0f;
    float m = wlane;
    float beta = 1.0f;

    for (int t = 0; t < T_OUT; t++) {
        float c23 = __shfl_sync(0xFFFFFFFFu, m, ORDER - 1);
        float up  = __shfl_up_sync(0xFFFFFFFFu, m, 1);
        float v;
        if (lane < ORDER)       v = m;
        else if (lane == ORDER) v = beta * bval;
        else                    v = 0.0f;
        __nv_bfloat16 hi = __float2bfloat16(v);
        __nv_bfloat16 lo = __float2bfloat16(v - __bfloat162float(hi));
        d_Bhi[t * KPAD + lane] = hi;
        d_Blo[t * KPAD + lane] = lo;
        if (lane < ORDER) m = fmaf(c23, wlane, (lane == 0) ? 0.0f : up);
        if (lane == ORDER) beta += c23;
    }

    __threadfence_block();
    __syncwarp();

    // fragment repack: mapping identical to R14's in-kernel Bs reads.
    for (int idx = lane; idx < NT * 2 * 32; idx += 32) {
        int nt = idx >> 6;
        int ks = (idx >> 5) & 1;
        int L  = idx & 31;
        int grp = L >> 2, qp = L & 3;
        int t  = nt * 8 + grp;
        int kb = ks * 16 + qp * 2;
        uint4 f;
        f.x = pack2(d_Bhi[t * KPAD + kb],     d_Bhi[t * KPAD + kb + 1]);
        f.y = pack2(d_Bhi[t * KPAD + kb + 8], d_Bhi[t * KPAD + kb + 9]);
        f.z = pack2(d_Blo[t * KPAD + kb],     d_Blo[t * KPAD + kb + 1]);
        f.w = pack2(d_Blo[t * KPAD + kb + 8], d_Blo[t * KPAD + kb + 9]);
        d_Bfrag[idx] = f;
    }
}

#define MMA_BF16(c, A, b0, b1)                                                \
    asm("mma.sync.aligned.m16n8k16.row.col.f32.bf16.bf16.f32 "                \
        "{%0,%1,%2,%3},{%4,%5,%6,%7},{%8,%9},{%0,%1,%2,%3};"                  \
        : "+f"((c)[0]), "+f"((c)[1]), "+f"((c)[2]), "+f"((c)[3])              \
        : "r"((A)[0]), "r"((A)[1]), "r"((A)[2]), "r"((A)[3]),                 \
          "r"(b0), "r"(b1))

__global__ __launch_bounds__(THREADS)
void ar_mma_kernel(const float* __restrict__ x,
                   float* __restrict__ out) {
    __shared__ __align__(16) char sm[SM_BYTES];
    __nv_bfloat16* As = reinterpret_cast<__nv_bfloat16*>(sm);  // hi, lo at AS_LO
    float* Cs = reinterpret_cast<float*>(sm);                  // overlay after A-frag loads

    const int tid = threadIdx.x;
    const int row0 = blockIdx.x * CTA_ROWS;
    const int b  = row0 >> 9;
    const int d0 = row0 & (D_DIM - 1);

    // --- stage A: window x[b, 312+k, d0+i], split bf16 hi/lo (coalesced in i)
    const float* xw = x + ((size_t)b * S_DIM + (S_DIM - ORDER)) * D_DIM + d0;
    for (int idx = tid; idx < ORDER * CTA_ROWS; idx += THREADS) {
        int k = idx >> 6, i = idx & 63;
        float v = __ldg(xw + (size_t)k * D_DIM + i);
        __nv_bfloat16 hi = __float2bfloat16(v);
        __nv_bfloat16 lo = __float2bfloat16(v - __bfloat162float(hi));
        As[i * KP + k] = hi;
        As[AS_LO + i * KP + k] = lo;
    }
    for (int idx = tid; idx < CTA_ROWS * (KPAD - ORDER); idx += THREADS) {
        int i = idx & 63, k = ORDER + (idx >> 6);
        As[i * KP + k] = __float2bfloat16((k == ORDER) ? 1.0f : 0.0f);
        As[AS_LO + i * KP + k] = __float2bfloat16(0.0f);
    }
    __syncthreads();

    const int wid = tid >> 5, lane = tid & 31;
    const int grp = lane >> 2, qp = lane & 3;
    const int r = wid * 16 + grp;

    // --- A fragments (nt-invariant): [split][kstep][4 regs]  (R14-verified)
    uint32_t a[2][2][4];
#pragma unroll
    for (int s = 0; s < 2; s++) {
        const int base = s ? AS_LO : 0;
#pragma unroll
        for (int ks = 0; ks < 2; ks++) {
            const int kb = ks * 16 + qp * 2;
            a[s][ks][0] = *reinterpret_cast<const uint32_t*>(&As[base + r * KP + kb]);
            a[s][ks][1] = *reinterpret_cast<const uint32_t*>(&As[base + (r + 8) * KP + kb]);
            a[s][ks][2] = *reinterpret_cast<const uint32_t*>(&As[base + r * KP + kb + 8]);
            a[s][ks][3] = *reinterpret_cast<const uint32_t*>(&As[base + (r + 8) * KP + kb + 8]);
        }
    }
    __syncthreads();   // A frags in regs; safe to overlay Cs

    // --- MMA mainloop: B fragments straight from L1-resident global buffer
    float acc[NT][4];
#pragma unroll
    for (int nt = 0; nt < NT; nt++)
#pragma unroll
        for (int c = 0; c < 4; c++) acc[nt][c] = 0.0f;

    const uint4* bf = d_Bfrag + lane;
#pragma unroll
    for (int nt = 0; nt < NT; nt++) {
        uint4 f0 = __ldg(bf + nt * 64);        // ks = 0
        uint4 f1 = __ldg(bf + nt * 64 + 32);   // ks = 1
        MMA_BF16(acc[nt], a[0][0], f0.x, f0.y);   // hi*hi  ks0
        MMA_BF16(acc[nt], a[0][1], f1.x, f1.y);   // hi*hi  ks1
        MMA_BF16(acc[nt], a[0][0], f0.z, f0.w);   // hi*lo  ks0
        MMA_BF16(acc[nt], a[0][1], f1.z, f1.w);   // hi*lo  ks1
        MMA_BF16(acc[nt], a[1][0], f0.x, f0.y);   // lo*hi  ks0
        MMA_BF16(acc[nt], a[1][1], f1.x, f1.y);   // lo*hi  ks1
    }
    __syncthreads();

    // --- C fragments -> SMEM [row=d][t] (pad 173 -> conflict-free col reads)
#pragma unroll
    for (int nt = 0; nt < NT; nt++) {
        const int n = nt * 8 + qp * 2;
        Cs[r * CP + n]           = acc[nt][0];
        Cs[r * CP + n + 1]       = acc[nt][1];
        Cs[(r + 8) * CP + n]     = acc[nt][2];
        Cs[(r + 8) * CP + n + 1] = acc[nt][3];
    }
    __syncthreads();

    // --- coalesced store: fixed t, adjacent d per lane
    float* ob = out + (size_t)b * T_OUT * D_DIM + d0;
    for (int idx = tid; idx < CTA_ROWS * T_OUT; idx += THREADS) {
        int t = idx >> 6, i = idx & 63;
        ob[(size_t)t * D_DIM + i] = Cs[i * CP + t];
    }
}

extern "C" void kernel_launch(void* const* d_in, const int* in_sizes, int n_in,
                              void* d_out, int out_size) {
    const float* x  = (const float*)d_in[0];   // [256, 336, 512]
    const float* W  = (const float*)d_in[1];   // [24, 1]
    const float* bs = (const float*)d_in[2];   // [1]
    float* out = (float*)d_out;                // [256, 168, 512]

    ar_prep_kernel<<<1, 32>>>(W, bs);
    const int n_ctas = (B_DIM * D_DIM) / CTA_ROWS;   // 2048
    ar_mma_kernel<<<n_ctas, THREADS>>>(x, out);
}

// round 16
// speedup vs baseline: 1.5102x; 1.5102x over previous
#include <cuda_runtime.h>
#include <cuda_bf16.h>
#include <cstdint>

// R16: AR(24) closed-form GEMM, single fused kernel.
//  - warp 0 of every CTA runs the 168-step coefficient shfl-recurrence
//    (R12/R14/R15-verified algebra) and writes bf16 hi/lo coefficients
//    DIRECTLY into SMEM in mma-fragment layout via halfword stores.
//  - A fragments built straight from 12 per-thread LDGs (no SMEM staging).
//  - 3-phase epilogue (7 n-tiles each) caps live accumulators at 28 regs:
//    ~70 regs total under launch_bounds(128,6) -> 6 CTAs/SM (was 4).
//
// Shapes: x [256,336,512] f32, W [24,1] f32, b [1] f32, out [256,168,512] f32

#define ORDER 24
#define T_OUT 168
#define D_DIM 512
#define B_DIM 256
#define S_DIM 336
#define THREADS 128
#define NT 21
#define PH_NT 7
#define PH_T 56            // 7 n-tiles * 8
#define CP 57              // Cs stride (odd -> conflict-free column reads)

static __device__ __forceinline__ unsigned short bf16_bits(float v) {
    __nv_bfloat16 b = __float2bfloat16(v);
    unsigned short u; __builtin_memcpy(&u, &b, 2); return u;
}
static __device__ __forceinline__ float bf16_val(float v) {
    return __bfloat162float(__float2bfloat16(v));
}
static __device__ __forceinline__ unsigned pack_hi(float v0, float v1) {
    return ((unsigned)bf16_bits(v1) << 16) | (unsigned)bf16_bits(v0);
}
static __device__ __forceinline__ unsigned pack_lo(float v0, float v1) {
    return pack_hi(v0 - bf16_val(v0), v1 - bf16_val(v1));
}

#define MMA_BF16(c, A, b0, b1)                                                \
    asm("mma.sync.aligned.m16n8k16.row.col.f32.bf16.bf16.f32 "                \
        "{%0,%1,%2,%3},{%4,%5,%6,%7},{%8,%9},{%0,%1,%2,%3};"                  \
        : "+f"((c)[0]), "+f"((c)[1]), "+f"((c)[2]), "+f"((c)[3])              \
        : "r"((A)[0]), "r"((A)[1]), "r"((A)[2]), "r"((A)[3]),                 \
          "r"(b0), "r"(b1))

__global__ __launch_bounds__(THREADS, 6)
void ar_fused_kernel(const float* __restrict__ x,
                     const float* __restrict__ W,
                     const float* __restrict__ bias,
                     float* __restrict__ out) {
    // BF: B fragments [nt][ks][lane] as uint4 {bh0,bh1,bl0,bl1}  (21504 B)
    // Cs: epilogue transpose buffer 64 x 57 f32                  (14592 B)
    __shared__ __align__(16) uint4 BF[NT * 2 * 32];
    __shared__ __align__(16) float Cs[64 * CP];

    const int tid  = threadIdx.x;
    const int wid  = tid >> 5, lane = tid & 31;
    const int grp  = lane >> 2, qp = lane & 3;
    const int r    = wid * 16 + grp;
    const int b    = blockIdx.x >> 3;
    const int d0   = (blockIdx.x & 7) << 6;

    unsigned bf_base, cs_base;
    asm("{ .reg .u64 t; cvta.to.shared.u64 t, %1; cvt.u32.u64 %0, t; }"
        : "=r"(bf_base) : "l"(BF));
    asm("{ .reg .u64 t; cvta.to.shared.u64 t, %1; cvt.u32.u64 %0, t; }"
        : "=r"(cs_base) : "l"(Cs));

    // ---- A: 12 direct LDGs -> fragment registers (R14-verified mapping).
    // rows {r, r+8}, k in {2qp,2qp+1, 2qp+8,2qp+9, 2qp+16,2qp+17}
    float v[2][6];
    {
        const float* xw = x + ((size_t)b * S_DIM + (S_DIM - ORDER)) * D_DIM + d0;
#pragma unroll
        for (int rr = 0; rr < 2; rr++) {
            const float* xr = xw + r + rr * 8;
            const int k0 = 2 * qp;
            v[rr][0] = __ldg(xr + (size_t)(k0)      * D_DIM);
            v[rr][1] = __ldg(xr + (size_t)(k0 + 1)  * D_DIM);
            v[rr][2] = __ldg(xr + (size_t)(k0 + 8)  * D_DIM);
            v[rr][3] = __ldg(xr + (size_t)(k0 + 9)  * D_DIM);
            v[rr][4] = __ldg(xr + (size_t)(k0 + 16) * D_DIM);
            v[rr][5] = __ldg(xr + (size_t)(k0 + 17) * D_DIM);
        }
    }
    uint32_t a[2][2][4];
#pragma unroll
    for (int rr = 0; rr < 2; rr++) {
        a[0][0][0 + rr] = pack_hi(v[rr][0], v[rr][1]);
        a[1][0][0 + rr] = pack_lo(v[rr][0], v[rr][1]);
        a[0][0][2 + rr] = pack_hi(v[rr][2], v[rr][3]);
        a[1][0][2 + rr] = pack_lo(v[rr][2], v[rr][3]);
        a[0][1][0 + rr] = pack_hi(v[rr][4], v[rr][5]);
        a[1][1][0 + rr] = pack_lo(v[rr][4], v[rr][5]);
    }
    {   // k = 24+2qp, 25+2qp: bias column (k==24 -> 1.0), else 0
        const unsigned cst = (qp == 0) ? 0x00003F80u : 0u;  // (bf16)1.0 in low half
        a[0][1][2] = cst; a[0][1][3] = cst;
        a[1][1][2] = 0u;  a[1][1][3] = 0u;
    }

    // ---- coefficient chain (warp 0): write B frags directly as halfwords.
    if (wid == 0) {
        const float bval = __ldg(bias);
        const float wlane = (lane < ORDER) ? __ldg(&W[lane]) : 0.0f;
        float m = wlane;
        float beta = 1.0f;
        // lane k -> fragment byte position (constant per lane)
        const int ks  = lane >> 4;
        const int km  = lane & 15;
        const int eps = km >> 3;          // component x(0)/y(1)
        const int rem = km & 7;
        const int qpf = rem >> 1;         // fragment lane's qp
        const int dlt = rem & 1;          // pair position
        const unsigned coff = (unsigned)(ks * 512 + qpf * 16 + eps * 4 + dlt * 2);

        for (int t = 0; t < T_OUT; t++) {
            float c23 = __shfl_sync(0xFFFFFFFFu, m, ORDER - 1);
            float up  = __shfl_up_sync(0xFFFFFFFFu, m, 1);
            float val;
            if (lane < ORDER)       val = m;
            else if (lane == ORDER) val = beta * bval;
            else                    val = 0.0f;
            unsigned short hb = bf16_bits(val);
            unsigned short lb = bf16_bits(val - bf16_val(val));
            // frag block for (nt = t>>3, grp = t&7)
            unsigned addr = bf_base + (unsigned)((t >> 3) * 1024 + (t & 7) * 64) + coff;
            asm volatile("st.shared.u16 [%0], %1;" :: "r"(addr), "h"(hb));
            asm volatile("st.shared.u16 [%0], %1;" :: "r"(addr + 8), "h"(lb));
            if (lane < ORDER) m = fmaf(c23, wlane, (lane == 0) ? 0.0f : up);
            if (lane == ORDER) beta += c23;
        }
    }
    __syncthreads();

    // ---- 3 phases: 7 n-tiles MMA -> Cs transpose -> coalesced store
    float* ob0 = out + (size_t)b * T_OUT * D_DIM + d0;
#pragma unroll 1
    for (int p = 0; p < 3; p++) {
        const int nt0 = p * PH_NT;
        float acc[PH_NT][4];
#pragma unroll
        for (int nt = 0; nt < PH_NT; nt++)
#pragma unroll
            for (int c = 0; c < 4; c++) acc[nt][c] = 0.0f;

#pragma unroll
        for (int nt = 0; nt < PH_NT; nt++) {
            uint4 f0, f1;
            unsigned ba = bf_base + (unsigned)((nt0 + nt) * 1024 + lane * 16);
            asm("ld.shared.v4.u32 {%0,%1,%2,%3}, [%4];"
                : "=r"(f0.x), "=r"(f0.y), "=r"(f0.z), "=r"(f0.w) : "r"(ba));
            asm("ld.shared.v4.u32 {%0,%1,%2,%3}, [%4];"
                : "=r"(f1.x), "=r"(f1.y), "=r"(f1.z), "=r"(f1.w) : "r"(ba + 512));
            MMA_BF16(acc[nt], a[0][0], f0.x, f0.y);   // hi*hi ks0
            MMA_BF16(acc[nt], a[0][1], f1.x, f1.y);   // hi*hi ks1
            MMA_BF16(acc[nt], a[0][0], f0.z, f0.w);   // hi*lo ks0
            MMA_BF16(acc[nt], a[0][1], f1.z, f1.w);   // hi*lo ks1
            MMA_BF16(acc[nt], a[1][0], f0.x, f0.y);   // lo*hi ks0
            MMA_BF16(acc[nt], a[1][1], f1.x, f1.y);   // lo*hi ks1
        }

        __syncthreads();   // previous phase's Cs reads complete
#pragma unroll
        for (int nt = 0; nt < PH_NT; nt++) {
            const int n = nt * 8 + qp * 2;
            Cs[r * CP + n]           = acc[nt][0];
            Cs[r * CP + n + 1]       = acc[nt][1];
            Cs[(r + 8) * CP + n]     = acc[nt][2];
            Cs[(r + 8) * CP + n + 1] = acc[nt][3];
        }
        __syncthreads();

        float* ob = ob0 + (size_t)(p * PH_T) * D_DIM;
#pragma unroll 4
        for (int idx = tid; idx < 64 * PH_T; idx += THREADS) {
            int t = idx >> 6, i = idx & 63;
            ob[(size_t)t * D_DIM + i] = Cs[i * CP + t];
        }
    }
}

extern "C" void kernel_launch(void* const* d_in, const int* in_sizes, int n_in,
                              void* d_out, int out_size) {
    const float* x  = (const float*)d_in[0];   // [256, 336, 512]
    const float* W  = (const float*)d_in[1];   // [24, 1]
    const float* bs = (const float*)d_in[2];   // [1]
    float* out = (float*)d_out;                // [256, 168, 512]

    const int n_ctas = (B_DIM * D_DIM) / 64;   // 2048
    ar_fused_kernel<<<n_ctas, THREADS>>>(x, W, bs, out);
}